// round 1
// baseline (speedup 1.0000x reference)
#include <cuda_runtime.h>
#include <cuda_bf16.h>

// SCT_Memory: out[B, N] = (inputs[B,D] @ features[N,D]^T) / 0.07
// B=256, D=256, N=100000 (derived from in_sizes at launch).
//
// R0: register-blocked fp32 SGEMM. BM=BN=128, BK=16, 256 threads, 8x8/thread.
// Both operands are K-major (row-major with D contiguous) -> coalesced float4
// global loads along D for both tiles. Smem padded (+4) to break STS conflicts.

#define BM 128
#define BN 128
#define BK 16
#define PAD 4   // stride 132: 4*132 mod 32 = 16 -> 2-way STS conflict max; float4-aligned reads

__global__ __launch_bounds__(256, 2)
void sct_sgemm_kernel(const float* __restrict__ A,   // [Bsz, D] inputs
                      const float* __restrict__ Bm,  // [N, D]   features
                      float* __restrict__ C,         // [Bsz, N]
                      int N, int D)
{
    __shared__ float As[BK][BM + PAD];
    __shared__ float Bs[BK][BN + PAD];

    const int tid = threadIdx.x;
    const int tx  = tid & 15;   // 0..15 -> n direction
    const int ty  = tid >> 4;   // 0..15 -> m direction

    const int m0 = blockIdx.y * BM;
    const int n0 = blockIdx.x * BN;

    float acc[8][8];
    #pragma unroll
    for (int i = 0; i < 8; i++)
        #pragma unroll
        for (int j = 0; j < 8; j++)
            acc[i][j] = 0.0f;

    for (int k0 = 0; k0 < D; k0 += BK) {
        // ---- load A tile [BM x BK] -> As[k][m] (transposed) ----
        // 128 rows * 4 float4 = 512 float4 loads, 2 per thread
        #pragma unroll
        for (int i = 0; i < 2; i++) {
            int f   = tid + i * 256;
            int row = f >> 2;       // 0..127 (m)
            int c4  = f & 3;        // which float4 along k
            float4 v = *(const float4*)&A[(m0 + row) * D + k0 + c4 * 4];
            As[c4 * 4 + 0][row] = v.x;
            As[c4 * 4 + 1][row] = v.y;
            As[c4 * 4 + 2][row] = v.z;
            As[c4 * 4 + 3][row] = v.w;
        }
        // ---- load B tile [BN x BK] -> Bs[k][n] (transposed), N-guarded ----
        #pragma unroll
        for (int i = 0; i < 2; i++) {
            int f   = tid + i * 256;
            int row = f >> 2;       // 0..127 (n)
            int c4  = f & 3;
            int n   = n0 + row;
            float4 v = (n < N) ? *(const float4*)&Bm[n * D + k0 + c4 * 4]
                               : make_float4(0.f, 0.f, 0.f, 0.f);
            Bs[c4 * 4 + 0][row] = v.x;
            Bs[c4 * 4 + 1][row] = v.y;
            Bs[c4 * 4 + 2][row] = v.z;
            Bs[c4 * 4 + 3][row] = v.w;
        }
        __syncthreads();

        // ---- compute ----
        #pragma unroll
        for (int k = 0; k < BK; k++) {
            float a[8], b[8];
            float4 a0 = *(const float4*)&As[k][ty * 8];
            float4 a1 = *(const float4*)&As[k][ty * 8 + 4];
            float4 b0 = *(const float4*)&Bs[k][tx * 8];
            float4 b1 = *(const float4*)&Bs[k][tx * 8 + 4];
            a[0]=a0.x; a[1]=a0.y; a[2]=a0.z; a[3]=a0.w;
            a[4]=a1.x; a[5]=a1.y; a[6]=a1.z; a[7]=a1.w;
            b[0]=b0.x; b[1]=b0.y; b[2]=b0.z; b[3]=b0.w;
            b[4]=b1.x; b[5]=b1.y; b[6]=b1.z; b[7]=b1.w;
            #pragma unroll
            for (int i = 0; i < 8; i++)
                #pragma unroll
                for (int j = 0; j < 8; j++)
                    acc[i][j] = fmaf(a[i], b[j], acc[i][j]);
        }
        __syncthreads();
    }

    // ---- store, scaled by 1/TEMP ----
    const float scale = 1.0f / 0.07f;
    #pragma unroll
    for (int i = 0; i < 8; i++) {
        int m = m0 + ty * 8 + i;
        #pragma unroll
        for (int j = 0; j < 2; j++) {
            int n = n0 + tx * 8 + j * 4;
            if (n + 3 < N) {
                float4 v;
                v.x = acc[i][j * 4 + 0] * scale;
                v.y = acc[i][j * 4 + 1] * scale;
                v.z = acc[i][j * 4 + 2] * scale;
                v.w = acc[i][j * 4 + 3] * scale;
                *(float4*)&C[m * N + n] = v;
            } else if (n < N) {
                for (int q = 0; q < 4 && n + q < N; q++)
                    C[m * N + n + q] = acc[i][j * 4 + q] * scale;
            }
        }
    }
}

extern "C" void kernel_launch(void* const* d_in, const int* in_sizes, int n_in,
                              void* d_out, int out_size)
{
    const float* inputs   = (const float*)d_in[0];  // [B, D] fp32
    // d_in[1] = indexes (unused), d_in[3] = momentum (unused)
    const float* features = (const float*)d_in[2];  // [N, D] fp32

    const int D   = 256;
    const int Bsz = in_sizes[0] / D;   // 256
    const int N   = in_sizes[2] / D;   // 100000

    float* out = (float*)d_out;

    dim3 grid((N + BN - 1) / BN, (Bsz + BM - 1) / BM);
    sct_sgemm_kernel<<<grid, 256>>>(inputs, features, out, N, D);
}

// round 3
// speedup vs baseline: 1.4757x; 1.4757x over previous
#include <cuda_runtime.h>
#include <cuda_bf16.h>
#include <cstdint>

// out[B=256, N] = (inputs @ features^T) / 0.07
// R2: mma.sync (HMMA) bf16-split GEMM. tcgen05 is NOT available (harness PTX
// target is compute_103 without the 'a' feature set), so tensor work goes
// through baseline mma.sync.m16n8k16 + ldmatrix.
//
// Per CTA: M=256 (full batch) x N=64, K=256 in 8 chunks of 32.
// 512 threads = 16 warps, warp tile 32x32 (2 mtiles x 4 ntiles of m16n8).
// Products: Ah*Fh + Ah*Fl + Al*Fh (bf16 split, rel_err ~1e-5).
// F converted fp32->bf16(hi,lo) in-kernel; A pre-split into device scratch.

#define KC 32
#define NITER 8
#define NT 64
#define ROWB 80u            // smem row stride bytes (40 bf16) -> conflict-free ldmatrix
#define OFF_AH 0u
#define OFF_AL 20480u       // 256*80
#define OFF_FH 40960u
#define OFF_FL 46080u       // +64*80
#define STAGE 51200u
#define SMEM_TOTAL (2 * 51200)
#define SCALE (1.0f / 0.07f)

__device__ __align__(16) __nv_bfloat16 g_Ah[256 * 256];
__device__ __align__(16) __nv_bfloat16 g_Al[256 * 256];

// ---------------- helpers ----------------
__device__ __forceinline__ uint32_t smem_u32(const void* p) {
    uint32_t r;
    asm("{ .reg .u64 t; cvta.to.shared.u64 t, %1; cvt.u32.u64 %0, t; }" : "=r"(r) : "l"(p));
    return r;
}
// pack two fp32 -> bf16x2: 'lo' goes to lower 16 bits (even k), 'hi' to upper.
__device__ __forceinline__ uint32_t pack_bf16x2(float hi, float lo) {
    uint32_t r;
    asm("cvt.rn.bf16x2.f32 %0, %1, %2;" : "=r"(r) : "f"(hi), "f"(lo));
    return r;
}
__device__ __forceinline__ void sts128(uint32_t a, uint4 v) {
    asm volatile("st.shared.v4.b32 [%0], {%1,%2,%3,%4};"
                 :: "r"(a), "r"(v.x), "r"(v.y), "r"(v.z), "r"(v.w) : "memory");
}
__device__ __forceinline__ void sts64(uint32_t a, uint32_t x, uint32_t y) {
    asm volatile("st.shared.v2.b32 [%0], {%1,%2};" :: "r"(a), "r"(x), "r"(y) : "memory");
}
__device__ __forceinline__ void ldm4(uint32_t* r, uint32_t a) {
    asm volatile("ldmatrix.sync.aligned.m8n8.x4.shared.b16 {%0,%1,%2,%3}, [%4];"
                 : "=r"(r[0]), "=r"(r[1]), "=r"(r[2]), "=r"(r[3]) : "r"(a));
}
__device__ __forceinline__ void ldm2(uint32_t* r, uint32_t a) {
    asm volatile("ldmatrix.sync.aligned.m8n8.x2.shared.b16 {%0,%1}, [%2];"
                 : "=r"(r[0]), "=r"(r[1]) : "r"(a));
}
__device__ __forceinline__ void mma16816(float* d, const uint32_t* a, const uint32_t* b) {
    asm volatile("mma.sync.aligned.m16n8k16.row.col.f32.bf16.bf16.f32 "
                 "{%0,%1,%2,%3}, {%4,%5,%6,%7}, {%8,%9}, {%0,%1,%2,%3};"
                 : "+f"(d[0]), "+f"(d[1]), "+f"(d[2]), "+f"(d[3])
                 : "r"(a[0]), "r"(a[1]), "r"(a[2]), "r"(a[3]), "r"(b[0]), "r"(b[1]));
}

// ---------------- A split kernel ----------------
__global__ void sct_splitA(const float* __restrict__ A) {
    int i = blockIdx.x * 256 + threadIdx.x;
    float f = A[i];
    __nv_bfloat16 h = __float2bfloat16(f);
    g_Ah[i] = h;
    g_Al[i] = __float2bfloat16(f - __bfloat162float(h));
}

// ---------------- main GEMM ----------------
__global__ __launch_bounds__(512, 1)
void sct_mma_kernel(const float* __restrict__ F, float* __restrict__ C, int N)
{
    extern __shared__ char smem[];
    const uint32_t sb = smem_u32(smem);
    const int tid  = threadIdx.x;
    const int lane = tid & 31;
    const int wid  = tid >> 5;
    const int n0   = blockIdx.x * NT;

    // ---- load assignments ----
    // A: threads 0-255 -> hi, 256-511 -> lo; each thread = one of 256 rows, 32 bf16.
    const int arow = tid & 255;
    const __nv_bfloat16* asrc = ((tid & 256) ? g_Al : g_Ah) + arow * 256;
    const uint32_t a_sts_off = ((tid & 256) ? OFF_AL : OFF_AH) + (uint32_t)arow * ROWB;
    // F: thread -> row = tid>>3 (0..63), 4 floats at col (tid&7)*4.
    const int frow = tid >> 3;
    const int fq   = tid & 7;
    const int fn   = n0 + frow;
    const bool fvalid = (fn < N);
    const float* fsrc = F + (size_t)fn * 256 + fq * 4;
    const uint32_t f_sts_h = OFF_FH + (uint32_t)frow * ROWB + (uint32_t)fq * 8;
    const uint32_t f_sts_l = OFF_FL + (uint32_t)frow * ROWB + (uint32_t)fq * 8;

    // ---- warp tiling: 8 m-warps x 2 n-warps; warp tile 32x32 ----
    const int wm = wid >> 1;
    const int wn = wid & 1;
    const int mbase = wm * 32;
    const int nb    = wn * 32;

    // fragment smem offsets (within stage)
    const uint32_t a_frag = (uint32_t)(mbase + (lane & 15)) * ROWB + (uint32_t)((lane >> 4) * 16);
    const uint32_t b_frag = (uint32_t)(nb + (lane & 7)) * ROWB + (uint32_t)(((lane >> 3) & 1) * 16);

    float acc[2][4][4];
    #pragma unroll
    for (int i = 0; i < 2; i++)
        #pragma unroll
        for (int j = 0; j < 4; j++)
            #pragma unroll
            for (int q = 0; q < 4; q++) acc[i][j][q] = 0.0f;

    uint4 pa0, pa1, pa2, pa3;
    float4 pf;

    auto prefetch = [&](int c) {
        const uint4* s = (const uint4*)(asrc + c * KC);
        pa0 = s[0]; pa1 = s[1]; pa2 = s[2]; pa3 = s[3];
        pf = fvalid ? *(const float4*)(fsrc + c * KC) : make_float4(0.f, 0.f, 0.f, 0.f);
    };
    auto store_stage = [&](int s) {
        const uint32_t st = sb + s * STAGE;
        const uint32_t ab = st + a_sts_off;
        sts128(ab,      pa0);
        sts128(ab + 16, pa1);
        sts128(ab + 32, pa2);
        sts128(ab + 48, pa3);
        // split F into hi/lo bf16
        float hx = __bfloat162float(__float2bfloat16(pf.x));
        float hy = __bfloat162float(__float2bfloat16(pf.y));
        float hz = __bfloat162float(__float2bfloat16(pf.z));
        float hw = __bfloat162float(__float2bfloat16(pf.w));
        uint32_t h0 = pack_bf16x2(hy, hx);
        uint32_t h1 = pack_bf16x2(hw, hz);
        uint32_t l0 = pack_bf16x2(pf.y - hy, pf.x - hx);
        uint32_t l1 = pack_bf16x2(pf.w - hw, pf.z - hz);
        sts64(st + f_sts_h, h0, h1);
        sts64(st + f_sts_l, l0, l1);
    };
    auto compute = [&](int s) {
        const uint32_t st = sb + s * STAGE;
        #pragma unroll
        for (int ks = 0; ks < 2; ks++) {
            const uint32_t ko = ks * 32;   // 16 bf16 = 32 bytes
            uint32_t bh[4][2], bl[4][2];
            #pragma unroll
            for (int j = 0; j < 4; j++) {
                ldm2(bh[j], st + OFF_FH + b_frag + (uint32_t)j * (8 * ROWB) + ko);
                ldm2(bl[j], st + OFF_FL + b_frag + (uint32_t)j * (8 * ROWB) + ko);
            }
            uint32_t a[2][4];
            #pragma unroll
            for (int i = 0; i < 2; i++)
                ldm4(a[i], st + OFF_AH + a_frag + (uint32_t)i * (16 * ROWB) + ko);
            #pragma unroll
            for (int i = 0; i < 2; i++)
                #pragma unroll
                for (int j = 0; j < 4; j++) {
                    mma16816(acc[i][j], a[i], bh[j]);
                    mma16816(acc[i][j], a[i], bl[j]);
                }
            #pragma unroll
            for (int i = 0; i < 2; i++)
                ldm4(a[i], st + OFF_AL + a_frag + (uint32_t)i * (16 * ROWB) + ko);
            #pragma unroll
            for (int i = 0; i < 2; i++)
                #pragma unroll
                for (int j = 0; j < 4; j++)
                    mma16816(acc[i][j], a[i], bh[j]);
        }
    };

    // ---- mainloop: double-buffered, register prefetch overlaps HMMA ----
    prefetch(0);
    store_stage(0);
    __syncthreads();
    for (int c = 0; c < NITER; c++) {
        if (c + 1 < NITER) prefetch(c + 1);
        compute(c & 1);
        if (c + 1 < NITER) {
            store_stage((c + 1) & 1);
            __syncthreads();
        }
    }

    // ---- epilogue ----
    #pragma unroll
    for (int i = 0; i < 2; i++) {
        const int m = mbase + i * 16 + (lane >> 2);
        #pragma unroll
        for (int j = 0; j < 4; j++) {
            const int n = n0 + nb + j * 8 + (lane & 3) * 2;
            float* p0 = C + (size_t)m * N + n;
            float* p1 = C + (size_t)(m + 8) * N + n;
            if (n + 1 < N) {
                float2 v0 = make_float2(acc[i][j][0] * SCALE, acc[i][j][1] * SCALE);
                float2 v1 = make_float2(acc[i][j][2] * SCALE, acc[i][j][3] * SCALE);
                *(float2*)p0 = v0;
                *(float2*)p1 = v1;
            } else if (n < N) {
                p0[0] = acc[i][j][0] * SCALE;
                p1[0] = acc[i][j][2] * SCALE;
            }
        }
    }
}

// ---------------- launch ----------------
extern "C" void kernel_launch(void* const* d_in, const int* in_sizes, int n_in,
                              void* d_out, int out_size)
{
    const float* inputs   = (const float*)d_in[0];  // [256, 256]
    const float* features = (const float*)d_in[2];  // [N, 256]
    const int D = 256;
    const int N = in_sizes[2] / D;

    sct_splitA<<<256, 256>>>(inputs);

    cudaFuncSetAttribute(sct_mma_kernel, cudaFuncAttributeMaxDynamicSharedMemorySize, SMEM_TOTAL);
    int grid = (N + NT - 1) / NT;
    sct_mma_kernel<<<grid, 512, SMEM_TOTAL>>>(features, (float*)d_out, N);
}

// round 4
// speedup vs baseline: 4.0753x; 2.7616x over previous
#include <cuda_runtime.h>
#include <cuda_fp16.h>
#include <cstdint>

// out[B=256, N] = (inputs @ features^T) / 0.07
// R3: single-product fp16 mma.sync GEMM (tcgen05 unavailable on compute_103).
// fp16 rn quantization error ~2e-4 global << 1e-3 threshold.
// CTA: M=256 x N=128, K=256 in 8 chunks of 32. 512 thr = 16 warps (4x4),
// warp tile 64x32. A pre-converted to fp16, staged via cp.async.cg (L1 bypass);
// F converted fp32->fp16 in-kernel. Double-buffered smem, stride 80B
// (conflict-free ldmatrix phases).

#define KC 32
#define NITER 8
#define NT 128
#define ROWB 80u
#define OFF_F 20480u           // A tile 256*80
#define STAGE 30720u           // + F tile 128*80
#define SMEM_TOTAL (2 * 30720)
#define SCALE (1.0f / 0.07f)

__device__ __align__(16) __half g_A16[256 * 256];

// ---------------- helpers ----------------
__device__ __forceinline__ uint32_t smem_u32(const void* p) {
    uint32_t r;
    asm("{ .reg .u64 t; cvta.to.shared.u64 t, %1; cvt.u32.u64 %0, t; }" : "=r"(r) : "l"(p));
    return r;
}
// pack two fp32 -> f16x2: 'lo' -> lower 16 bits, 'hi' -> upper.
__device__ __forceinline__ uint32_t pack_f16x2(float hi, float lo) {
    uint32_t r;
    asm("cvt.rn.f16x2.f32 %0, %1, %2;" : "=r"(r) : "f"(hi), "f"(lo));
    return r;
}
__device__ __forceinline__ void sts128(uint32_t a, uint32_t x, uint32_t y, uint32_t z, uint32_t w) {
    asm volatile("st.shared.v4.b32 [%0], {%1,%2,%3,%4};"
                 :: "r"(a), "r"(x), "r"(y), "r"(z), "r"(w) : "memory");
}
__device__ __forceinline__ void ldm4(uint32_t* r, uint32_t a) {
    asm volatile("ldmatrix.sync.aligned.m8n8.x4.shared.b16 {%0,%1,%2,%3}, [%4];"
                 : "=r"(r[0]), "=r"(r[1]), "=r"(r[2]), "=r"(r[3]) : "r"(a));
}
__device__ __forceinline__ void mma16816(float* d, const uint32_t* a, const uint32_t* b) {
    asm volatile("mma.sync.aligned.m16n8k16.row.col.f32.f16.f16.f32 "
                 "{%0,%1,%2,%3}, {%4,%5,%6,%7}, {%8,%9}, {%0,%1,%2,%3};"
                 : "+f"(d[0]), "+f"(d[1]), "+f"(d[2]), "+f"(d[3])
                 : "r"(a[0]), "r"(a[1]), "r"(a[2]), "r"(a[3]), "r"(b[0]), "r"(b[1]));
}
__device__ __forceinline__ void cp_async16(uint32_t dst, const void* src) {
    asm volatile("cp.async.cg.shared.global [%0], [%1], 16;" :: "r"(dst), "l"(src) : "memory");
}
#define CP_COMMIT asm volatile("cp.async.commit_group;" ::: "memory")
#define CP_WAIT0  asm volatile("cp.async.wait_group 0;" ::: "memory")

// ---------------- A convert kernel ----------------
__global__ void sct_cvtA(const float* __restrict__ A) {
    int i = blockIdx.x * 256 + threadIdx.x;   // 65536 elems
    g_A16[i] = __float2half_rn(A[i]);
}

// ---------------- main GEMM ----------------
__global__ __launch_bounds__(512, 1)
void sct_mma_kernel(const float* __restrict__ F, float* __restrict__ C, int N)
{
    extern __shared__ char smem[];
    const uint32_t sb = smem_u32(smem);
    const int tid  = threadIdx.x;
    const int lane = tid & 31;
    const int wid  = tid >> 5;
    const int n0   = blockIdx.x * NT;

    // A staging: 1024 16B granules per chunk, 2 per thread (rows r, r+128)
    const int ar = tid >> 2;          // 0..127
    const int aq = tid & 3;           // 16B quarter within 64B row
    const uint32_t a_dst = (uint32_t)ar * ROWB + (uint32_t)aq * 16;
    const __half* a_src = g_A16 + ar * 256 + aq * 8;

    // F staging: row = tid>>2 (0..127), 8 floats at (tid&3)*8
    const int frow = tid >> 2;
    const int fq   = tid & 3;
    const int fn   = n0 + frow;
    const bool fvalid = (fn < N);
    const float* fsrc = F + (size_t)fn * 256 + fq * 8;
    const uint32_t f_sts = OFF_F + (uint32_t)frow * ROWB + (uint32_t)fq * 16;

    // warp tiling: 4 m-warps x 4 n-warps, warp tile 64x32
    const int wm = wid & 3;
    const int wn = wid >> 2;
    const int mbase = wm * 64;
    const int nb    = wn * 32;

    const uint32_t afrag = (uint32_t)(mbase + (lane & 15)) * ROWB + (uint32_t)((lane >> 4) * 16);
    const uint32_t bfrag = (uint32_t)(nb + (lane & 7) + ((lane >> 4) << 3)) * ROWB
                         + (uint32_t)(((lane >> 3) & 1) << 4);

    float acc[4][4][4];
    #pragma unroll
    for (int i = 0; i < 4; i++)
        #pragma unroll
        for (int j = 0; j < 4; j++)
            #pragma unroll
            for (int q = 0; q < 4; q++) acc[i][j][q] = 0.0f;

    float4 pf0, pf1;

    auto cpA = [&](int s, int c) {
        const uint32_t dst = sb + s * STAGE + a_dst;
        const __half* src = a_src + c * KC;
        cp_async16(dst, src);
        cp_async16(dst + 128 * ROWB, src + 128 * 256);
    };
    auto ldgF = [&](int c) {
        if (fvalid) {
            pf0 = *(const float4*)(fsrc + c * KC);
            pf1 = *(const float4*)(fsrc + c * KC + 4);
        } else {
            pf0 = pf1 = make_float4(0.f, 0.f, 0.f, 0.f);
        }
    };
    auto stsF = [&](int s) {
        uint32_t h0 = pack_f16x2(pf0.y, pf0.x);
        uint32_t h1 = pack_f16x2(pf0.w, pf0.z);
        uint32_t h2 = pack_f16x2(pf1.y, pf1.x);
        uint32_t h3 = pack_f16x2(pf1.w, pf1.z);
        sts128(sb + s * STAGE + f_sts, h0, h1, h2, h3);
    };
    auto compute = [&](int s) {
        const uint32_t st = sb + s * STAGE;
        #pragma unroll
        for (int ks = 0; ks < 2; ks++) {
            const uint32_t ko = ks * 32;
            uint32_t b0[4], b1[4], a[4][4];
            ldm4(b0, st + OFF_F + bfrag + ko);                 // n-tiles 0,1
            ldm4(b1, st + OFF_F + bfrag + 16 * ROWB + ko);     // n-tiles 2,3
            #pragma unroll
            for (int i = 0; i < 4; i++)
                ldm4(a[i], st + afrag + (uint32_t)i * (16 * ROWB) + ko);
            #pragma unroll
            for (int i = 0; i < 4; i++) {
                mma16816(acc[i][0], a[i], b0 + 0);
                mma16816(acc[i][1], a[i], b0 + 2);
                mma16816(acc[i][2], a[i], b1 + 0);
                mma16816(acc[i][3], a[i], b1 + 2);
            }
        }
    };

    // ---- prologue ----
    cpA(0, 0); CP_COMMIT;
    ldgF(0);
    stsF(0);
    CP_WAIT0;
    __syncthreads();

    // ---- mainloop ----
    for (int c = 0; c < NITER; c++) {
        const int cur = c & 1;
        const int nxt = cur ^ 1;
        if (c + 1 < NITER) {
            cpA(nxt, c + 1); CP_COMMIT;
            ldgF(c + 1);
        }
        compute(cur);
        if (c + 1 < NITER) {
            stsF(nxt);
            CP_WAIT0;
            __syncthreads();
        }
    }

    // ---- epilogue ----
    #pragma unroll
    for (int i = 0; i < 4; i++) {
        const int m = mbase + i * 16 + (lane >> 2);
        #pragma unroll
        for (int j = 0; j < 4; j++) {
            const int n = n0 + nb + j * 8 + (lane & 3) * 2;
            if (n < N) {   // N even, n even -> n+1 valid too
                float* p0 = C + (size_t)m * N + n;
                float* p1 = C + (size_t)(m + 8) * N + n;
                *(float2*)p0 = make_float2(acc[i][j][0] * SCALE, acc[i][j][1] * SCALE);
                *(float2*)p1 = make_float2(acc[i][j][2] * SCALE, acc[i][j][3] * SCALE);
            }
        }
    }
}

// ---------------- launch ----------------
extern "C" void kernel_launch(void* const* d_in, const int* in_sizes, int n_in,
                              void* d_out, int out_size)
{
    const float* inputs   = (const float*)d_in[0];  // [256, 256]
    const float* features = (const float*)d_in[2];  // [N, 256]
    const int D = 256;
    const int N = in_sizes[2] / D;

    sct_cvtA<<<256, 256>>>(inputs);

    cudaFuncSetAttribute(sct_mma_kernel, cudaFuncAttributeMaxDynamicSharedMemorySize, SMEM_TOTAL);
    int grid = (N + NT - 1) / NT;
    sct_mma_kernel<<<grid, 512, SMEM_TOTAL>>>(features, (float*)d_out, N);
}